// round 9
// baseline (speedup 1.0000x reference)
#include <cuda_runtime.h>
#include <cuda_bf16.h>
#include <cuda_fp8.h>
#include <math.h>

// ----- scratch (no allocations allowed) -----
#define NODE_CAP 131072
__device__ float g_node_sum[NODE_CAP];
// fp8(e4m3) copies of Q,K: one row = 64 fp8 = 64 B = 4 uint4
__device__ uint4 gQ8[NODE_CAP * 4];
__device__ uint4 gK8[NODE_CAP * 4];

__device__ __forceinline__ unsigned pack4_fp8(float4 a) {
    unsigned short lo = __nv_cvt_float2_to_fp8x2(make_float2(a.x, a.y), __NV_SATFINITE, __NV_E4M3);
    unsigned short hi = __nv_cvt_float2_to_fp8x2(make_float2(a.z, a.w), __NV_SATFINITE, __NV_E4M3);
    return (unsigned)lo | ((unsigned)hi << 16);
}

// fp32 -> fp8 conversion fused with zeroing. Each thread handles exactly two
// fixed indices (i and i+T), fully unrolled -> 16 independent LDG.128 in
// flight, perfectly balanced work, no ragged grid-stride loop.
__global__ void convert_zero_kernel(const float4* __restrict__ Q,
                                    const float4* __restrict__ K,
                                    float* __restrict__ out,
                                    int total4, int num_nodes, int num_graphs) {
    int i0 = blockIdx.x * blockDim.x + threadIdx.x;
    int T  = gridDim.x * blockDim.x;
    int i1 = i0 + T;
    bool p0 = (i0 < total4);
    bool p1 = (i1 < total4);

    if (i0 < num_nodes) g_node_sum[i0] = 0.0f;
    if (i1 < num_nodes) g_node_sum[i1] = 0.0f;
    if (i0 < num_graphs) out[i0] = 0.0f;

    // Q for both indices
    float4 qa0, qa1, qa2, qa3, qb0, qb1, qb2, qb3;
    if (p0) { const float4* p = Q + i0 * 4; qa0 = p[0]; qa1 = p[1]; qa2 = p[2]; qa3 = p[3]; }
    if (p1) { const float4* p = Q + i1 * 4; qb0 = p[0]; qb1 = p[1]; qb2 = p[2]; qb3 = p[3]; }
    if (p0) {
        uint4 o; o.x = pack4_fp8(qa0); o.y = pack4_fp8(qa1);
        o.z = pack4_fp8(qa2); o.w = pack4_fp8(qa3);
        gQ8[i0] = o;
    }
    if (p1) {
        uint4 o; o.x = pack4_fp8(qb0); o.y = pack4_fp8(qb1);
        o.z = pack4_fp8(qb2); o.w = pack4_fp8(qb3);
        gQ8[i1] = o;
    }

    // K for both indices
    if (p0) { const float4* p = K + i0 * 4; qa0 = p[0]; qa1 = p[1]; qa2 = p[2]; qa3 = p[3]; }
    if (p1) { const float4* p = K + i1 * 4; qb0 = p[0]; qb1 = p[1]; qb2 = p[2]; qb3 = p[3]; }
    if (p0) {
        uint4 o; o.x = pack4_fp8(qa0); o.y = pack4_fp8(qa1);
        o.z = pack4_fp8(qa2); o.w = pack4_fp8(qa3);
        gK8[i0] = o;
    }
    if (p1) {
        uint4 o; o.x = pack4_fp8(qb0); o.y = pack4_fp8(qb1);
        o.z = pack4_fp8(qb2); o.w = pack4_fp8(qb3);
        gK8[i1] = o;
    }
}

__device__ __forceinline__ float dot_fp8_u4(uint4 q, uint4 k) {
    __half2 acc = __floats2half2_rn(0.0f, 0.0f);
    #pragma unroll
    for (int j = 0; j < 4; j++) {
        unsigned qw = (&q.x)[j];
        unsigned kw = (&k.x)[j];
        __half2_raw q0 = __nv_cvt_fp8x2_to_halfraw2((__nv_fp8x2_storage_t)(qw & 0xffffu), __NV_E4M3);
        __half2_raw q1 = __nv_cvt_fp8x2_to_halfraw2((__nv_fp8x2_storage_t)(qw >> 16),     __NV_E4M3);
        __half2_raw k0 = __nv_cvt_fp8x2_to_halfraw2((__nv_fp8x2_storage_t)(kw & 0xffffu), __NV_E4M3);
        __half2_raw k1 = __nv_cvt_fp8x2_to_halfraw2((__nv_fp8x2_storage_t)(kw >> 16),     __NV_E4M3);
        acc = __hfma2(*(__half2*)&q0, *(__half2*)&k0, acc);
        acc = __hfma2(*(__half2*)&q1, *(__half2*)&k1, acc);
    }
    float2 f = __half22float2(acc);
    return f.x + f.y;
}

// 4 lanes per edge, 2 edges per group slot -> 16 edges per warp (MLP=4: the
// measured sweet spot; MLP=8 regressed 2x via L1tex queue depth).
// After the xor-butterfly all 4 lanes hold the full dot, so lane 0 handles
// edge0's atomic and lane 1 handles edge1's -> shorter serial atomic chain.
__global__ void edge_kernel(const int* __restrict__ c,
                            const int* __restrict__ u,
                            int num_edges) {
    const unsigned FULL = 0xffffffffu;
    int lane = threadIdx.x & 31;
    int grp  = lane >> 2;        // slot within warp (0..7)
    int li   = lane & 3;         // lane within 4-lane group
    int warp_id = (blockIdx.x * (blockDim.x >> 5)) + (threadIdx.x >> 5);
    int base = warp_id * 16;
    int e0 = base + grp;
    int e1 = base + 8 + grp;

    bool v0 = (e0 < num_edges);
    bool v1 = (e1 < num_edges);

    int c0 = 0, u0 = 0, c1 = 0, u1 = 0;
    if (v0) { c0 = c[e0]; u0 = u[e0]; }
    if (v1) { c1 = c[e1]; u1 = u[e1]; }

    float d0 = 0.0f, d1 = 0.0f;
    if (v0) {
        uint4 q = gQ8[c0 * 4 + li];
        uint4 k = gK8[u0 * 4 + li];
        d0 = dot_fp8_u4(q, k);
    }
    if (v1) {
        uint4 q = gQ8[c1 * 4 + li];
        uint4 k = gK8[u1 * 4 + li];
        d1 = dot_fp8_u4(q, k);
    }

    d0 += __shfl_xor_sync(FULL, d0, 1);
    d0 += __shfl_xor_sync(FULL, d0, 2);
    d1 += __shfl_xor_sync(FULL, d1, 1);
    d1 += __shfl_xor_sync(FULL, d1, 2);

    if (li == 0 && v0) atomicAdd(&g_node_sum[c0], __expf(d0 * 0.125f));
    if (li == 1 && v1) atomicAdd(&g_node_sum[c1], __expf(d1 * 0.125f));
}

// Per node: lse = log(sum) (0 for empty). batch is sorted -> warp-segmented
// reduction, only segment heads hit the per-graph atomic.
__global__ void node_kernel(const int* __restrict__ batch,
                            float* __restrict__ out,
                            int num_nodes) {
    const unsigned FULL = 0xffffffffu;
    int n = blockIdx.x * blockDim.x + threadIdx.x;
    int lane = threadIdx.x & 31;

    bool valid = (n < num_nodes);
    float v = 0.0f;
    int b = -1;
    if (valid) {
        float s = g_node_sum[n];
        v = (s > 0.0f) ? __logf(s) : 0.0f;
        b = batch[n];
    }
    #pragma unroll
    for (int off = 1; off < 32; off <<= 1) {
        float ov = __shfl_down_sync(FULL, v, off);
        int   ob = __shfl_down_sync(FULL, b, off);
        if (lane + off < 32 && ob == b) v += ov;
    }
    int bprev = __shfl_up_sync(FULL, b, 1);
    bool head = (lane == 0) || (bprev != b);
    if (valid && head) {
        atomicAdd(&out[b], v);
    }
}

extern "C" void kernel_launch(void* const* d_in, const int* in_sizes, int n_in,
                              void* d_out, int out_size) {
    const float4* Q   = (const float4*)d_in[0];
    const float4* K   = (const float4*)d_in[1];
    const int* c      = (const int*)d_in[2];
    const int* u      = (const int*)d_in[3];
    const int* batch  = (const int*)d_in[4];

    int num_nodes  = in_sizes[0] / 64;
    int num_edges  = in_sizes[2];
    int num_graphs = out_size;
    float* out = (float*)d_out;

    // fp32 -> fp8 conversion (2 fixed indices per thread) + zero node_sum/out
    {
        int total4 = num_nodes * 4;
        int blocks = (total4 + 2 * 256 - 1) / (2 * 256);
        convert_zero_kernel<<<blocks, 256>>>(Q, K, out, total4,
                                             num_nodes, num_graphs);
    }
    // edges: 4 lanes per edge, 16 edges per warp (2 per slot, MLP=4)
    {
        int threads = 256;                         // 8 warps -> 128 edges per block
        int edges_per_block = (threads / 32) * 16;
        int blocks = (num_edges + edges_per_block - 1) / edges_per_block;
        edge_kernel<<<blocks, threads>>>(c, u, num_edges);
    }
    // nodes -> per-graph energy (warp-aggregated atomics)
    {
        int blocks = (num_nodes + 511) / 512;
        node_kernel<<<blocks, 512>>>(batch, out, num_nodes);
    }
}

// round 10
// speedup vs baseline: 1.0500x; 1.0500x over previous
#include <cuda_runtime.h>
#include <cuda_bf16.h>
#include <cuda_fp8.h>
#include <math.h>

// ----- scratch (no allocations allowed) -----
#define NODE_CAP 131072
__device__ float g_node_sum[NODE_CAP];
// fp8(e4m3) copies of Q,K: one row = 64 fp8 = 64 B = 4 uint4
__device__ uint4 gQ8[NODE_CAP * 4];
__device__ uint4 gK8[NODE_CAP * 4];

// --- PDL primitives (sm_90+) ---
__device__ __forceinline__ void pdl_wait() {
    asm volatile("griddepcontrol.wait;" ::: "memory");
}
__device__ __forceinline__ void pdl_launch_dependents() {
    asm volatile("griddepcontrol.launch_dependents;" ::: "memory");
}

__device__ __forceinline__ unsigned pack4_fp8(float4 a) {
    unsigned short lo = __nv_cvt_float2_to_fp8x2(make_float2(a.x, a.y), __NV_SATFINITE, __NV_E4M3);
    unsigned short hi = __nv_cvt_float2_to_fp8x2(make_float2(a.z, a.w), __NV_SATFINITE, __NV_E4M3);
    return (unsigned)lo | ((unsigned)hi << 16);
}

// fp32 -> fp8 conversion (16 floats of Q and K per index) fused with zeroing of
// g_node_sum and out. Grid-stride, wave-balanced grid (148 SMs x 8 CTAs).
// (Round-8 champion body: measured 12.1us.)
__global__ void convert_zero_kernel(const float4* __restrict__ Q,
                                    const float4* __restrict__ K,
                                    float* __restrict__ out,
                                    int total4, int num_nodes, int num_graphs) {
    int stride = gridDim.x * blockDim.x;
    for (int i = blockIdx.x * blockDim.x + threadIdx.x; i < total4; i += stride) {
        if (i < num_nodes) g_node_sum[i] = 0.0f;
        if (i < num_graphs) out[i] = 0.0f;
        uint4 o;
        {
            const float4* p = Q + i * 4;
            float4 a0 = p[0], a1 = p[1], a2 = p[2], a3 = p[3];
            o.x = pack4_fp8(a0); o.y = pack4_fp8(a1);
            o.z = pack4_fp8(a2); o.w = pack4_fp8(a3);
            gQ8[i] = o;
        }
        {
            const float4* p = K + i * 4;
            float4 a0 = p[0], a1 = p[1], a2 = p[2], a3 = p[3];
            o.x = pack4_fp8(a0); o.y = pack4_fp8(a1);
            o.z = pack4_fp8(a2); o.w = pack4_fp8(a3);
            gK8[i] = o;
        }
    }
    pdl_launch_dependents();
}

__device__ __forceinline__ float dot_fp8_u4(uint4 q, uint4 k) {
    __half2 acc = __floats2half2_rn(0.0f, 0.0f);
    #pragma unroll
    for (int j = 0; j < 4; j++) {
        unsigned qw = (&q.x)[j];
        unsigned kw = (&k.x)[j];
        __half2_raw q0 = __nv_cvt_fp8x2_to_halfraw2((__nv_fp8x2_storage_t)(qw & 0xffffu), __NV_E4M3);
        __half2_raw q1 = __nv_cvt_fp8x2_to_halfraw2((__nv_fp8x2_storage_t)(qw >> 16),     __NV_E4M3);
        __half2_raw k0 = __nv_cvt_fp8x2_to_halfraw2((__nv_fp8x2_storage_t)(kw & 0xffffu), __NV_E4M3);
        __half2_raw k1 = __nv_cvt_fp8x2_to_halfraw2((__nv_fp8x2_storage_t)(kw >> 16),     __NV_E4M3);
        acc = __hfma2(*(__half2*)&q0, *(__half2*)&k0, acc);
        acc = __hfma2(*(__half2*)&q1, *(__half2*)&k1, acc);
    }
    float2 f = __half22float2(acc);
    return f.x + f.y;
}

// 4 lanes per edge, 2 edges per group slot -> 16 edges per warp (MLP=4 champion).
// PDL: c/u index loads are independent of convert's output -> issue them BEFORE
// griddepcontrol.wait so they overlap the convert tail. Gather after the wait.
__global__ void edge_kernel(const int* __restrict__ c,
                            const int* __restrict__ u,
                            int num_edges) {
    const unsigned FULL = 0xffffffffu;
    int lane = threadIdx.x & 31;
    int grp  = lane >> 2;        // slot within warp (0..7)
    int li   = lane & 3;         // lane within 4-lane group
    int warp_id = (blockIdx.x * (blockDim.x >> 5)) + (threadIdx.x >> 5);
    int base = warp_id * 16;
    int e0 = base + grp;
    int e1 = base + 8 + grp;

    bool v0 = (e0 < num_edges);
    bool v1 = (e1 < num_edges);

    int c0 = 0, u0 = 0, c1 = 0, u1 = 0;
    if (v0) { c0 = c[e0]; u0 = u[e0]; }
    if (v1) { c1 = c[e1]; u1 = u[e1]; }

    // Wait for convert grid to complete before touching gQ8/gK8/g_node_sum.
    pdl_wait();

    float d0 = 0.0f, d1 = 0.0f;
    if (v0) {
        uint4 q = gQ8[c0 * 4 + li];
        uint4 k = gK8[u0 * 4 + li];
        d0 = dot_fp8_u4(q, k);
    }
    if (v1) {
        uint4 q = gQ8[c1 * 4 + li];
        uint4 k = gK8[u1 * 4 + li];
        d1 = dot_fp8_u4(q, k);
    }

    d0 += __shfl_xor_sync(FULL, d0, 1);
    d0 += __shfl_xor_sync(FULL, d0, 2);
    d1 += __shfl_xor_sync(FULL, d1, 1);
    d1 += __shfl_xor_sync(FULL, d1, 2);

    if (li == 0) {
        if (v0) atomicAdd(&g_node_sum[c0], __expf(d0 * 0.125f));
        if (v1) atomicAdd(&g_node_sum[c1], __expf(d1 * 0.125f));
    }

    pdl_launch_dependents();
}

// Per node: lse = log(sum) (0 for empty). batch is sorted -> warp-segmented
// reduction, only segment heads hit the per-graph atomic.
// PDL: batch load is independent of edge output -> load before the wait.
__global__ void node_kernel(const int* __restrict__ batch,
                            float* __restrict__ out,
                            int num_nodes) {
    const unsigned FULL = 0xffffffffu;
    int n = blockIdx.x * blockDim.x + threadIdx.x;
    int lane = threadIdx.x & 31;

    bool valid = (n < num_nodes);
    int b = -1;
    if (valid) b = batch[n];

    // Wait for edge grid (g_node_sum complete; transitively, out zeroed).
    pdl_wait();

    float v = 0.0f;
    if (valid) {
        float s = g_node_sum[n];
        v = (s > 0.0f) ? __logf(s) : 0.0f;
    }
    #pragma unroll
    for (int off = 1; off < 32; off <<= 1) {
        float ov = __shfl_down_sync(FULL, v, off);
        int   ob = __shfl_down_sync(FULL, b, off);
        if (lane + off < 32 && ob == b) v += ov;
    }
    int bprev = __shfl_up_sync(FULL, b, 1);
    bool head = (lane == 0) || (bprev != b);
    if (valid && head) {
        atomicAdd(&out[b], v);
    }
}

extern "C" void kernel_launch(void* const* d_in, const int* in_sizes, int n_in,
                              void* d_out, int out_size) {
    const float4* Q   = (const float4*)d_in[0];
    const float4* K   = (const float4*)d_in[1];
    const int* c      = (const int*)d_in[2];
    const int* u      = (const int*)d_in[3];
    const int* batch  = (const int*)d_in[4];

    int num_nodes  = in_sizes[0] / 64;
    int num_edges  = in_sizes[2];
    int num_graphs = out_size;
    float* out = (float*)d_out;

    // 1) convert + zero (normal launch)
    {
        int total4 = num_nodes * 4;
        int blocks = 148 * 8;
        convert_zero_kernel<<<blocks, 256>>>(Q, K, out, total4,
                                             num_nodes, num_graphs);
    }
    // 2) edge kernel, PDL-dependent on convert
    {
        int threads = 256;
        int edges_per_block = (threads / 32) * 16;   // 128
        int blocks = (num_edges + edges_per_block - 1) / edges_per_block;

        cudaLaunchConfig_t cfg = {};
        cfg.gridDim = dim3((unsigned)blocks);
        cfg.blockDim = dim3((unsigned)threads);
        cudaLaunchAttribute attr[1];
        attr[0].id = cudaLaunchAttributeProgrammaticStreamSerialization;
        attr[0].val.programmaticStreamSerializationAllowed = 1;
        cfg.attrs = attr;
        cfg.numAttrs = 1;
        cudaLaunchKernelEx(&cfg, edge_kernel, c, u, num_edges);
    }
    // 3) node kernel, PDL-dependent on edge
    {
        int blocks = (num_nodes + 511) / 512;

        cudaLaunchConfig_t cfg = {};
        cfg.gridDim = dim3((unsigned)blocks);
        cfg.blockDim = dim3(512);
        cudaLaunchAttribute attr[1];
        attr[0].id = cudaLaunchAttributeProgrammaticStreamSerialization;
        attr[0].val.programmaticStreamSerializationAllowed = 1;
        cfg.attrs = attr;
        cfg.numAttrs = 1;
        cudaLaunchKernelEx(&cfg, node_kernel, batch, out, num_nodes);
    }
}

// round 11
// speedup vs baseline: 1.1237x; 1.0702x over previous
#include <cuda_runtime.h>
#include <cuda_bf16.h>
#include <cuda_fp8.h>
#include <math.h>

// ----- scratch (no allocations allowed) -----
#define NODE_CAP 131072
__device__ float g_node_sum[NODE_CAP];
// fp8(e4m3) copies of Q,K: one row = 64 fp8 = 64 B = 4 uint4
__device__ uint4 gQ8[NODE_CAP * 4];
__device__ uint4 gK8[NODE_CAP * 4];

// --- PDL primitives (sm_90+) ---
__device__ __forceinline__ void pdl_wait() {
    asm volatile("griddepcontrol.wait;" ::: "memory");
}
__device__ __forceinline__ void pdl_launch_dependents() {
    asm volatile("griddepcontrol.launch_dependents;" ::: "memory");
}

__device__ __forceinline__ unsigned pack4_fp8(float4 a) {
    unsigned short lo = __nv_cvt_float2_to_fp8x2(make_float2(a.x, a.y), __NV_SATFINITE, __NV_E4M3);
    unsigned short hi = __nv_cvt_float2_to_fp8x2(make_float2(a.z, a.w), __NV_SATFINITE, __NV_E4M3);
    return (unsigned)lo | ((unsigned)hi << 16);
}

// fp32 -> fp8 conversion, TRANSPOSED mapping: thread i handles ONE float4 at
// global float4-index i (lanes 16B apart -> each LDG.128 is a single coalesced
// 512B warp request; the 1-uint packed result makes STG.32 a coalesced 128B
// warp store). Grid-stride over num_nodes*16 with wave-balanced 148x8 grid.
// Fused zeroing of g_node_sum and out.
__global__ void convert_zero_kernel(const float4* __restrict__ Q,
                                    const float4* __restrict__ K,
                                    float* __restrict__ out,
                                    int total16 /* num_nodes*16 */,
                                    int num_nodes, int num_graphs) {
    unsigned* dQ = (unsigned*)gQ8;
    unsigned* dK = (unsigned*)gK8;
    int stride = gridDim.x * blockDim.x;
    int i = blockIdx.x * blockDim.x + threadIdx.x;
    if (i < num_nodes) g_node_sum[i] = 0.0f;
    if (i < num_graphs) out[i] = 0.0f;
    for (; i < total16; i += stride) {
        float4 q = Q[i];
        float4 k = K[i];
        dQ[i] = pack4_fp8(q);
        dK[i] = pack4_fp8(k);
    }
    pdl_launch_dependents();
}

__device__ __forceinline__ float dot_fp8_u4(uint4 q, uint4 k) {
    __half2 acc = __floats2half2_rn(0.0f, 0.0f);
    #pragma unroll
    for (int j = 0; j < 4; j++) {
        unsigned qw = (&q.x)[j];
        unsigned kw = (&k.x)[j];
        __half2_raw q0 = __nv_cvt_fp8x2_to_halfraw2((__nv_fp8x2_storage_t)(qw & 0xffffu), __NV_E4M3);
        __half2_raw q1 = __nv_cvt_fp8x2_to_halfraw2((__nv_fp8x2_storage_t)(qw >> 16),     __NV_E4M3);
        __half2_raw k0 = __nv_cvt_fp8x2_to_halfraw2((__nv_fp8x2_storage_t)(kw & 0xffffu), __NV_E4M3);
        __half2_raw k1 = __nv_cvt_fp8x2_to_halfraw2((__nv_fp8x2_storage_t)(kw >> 16),     __NV_E4M3);
        acc = __hfma2(*(__half2*)&q0, *(__half2*)&k0, acc);
        acc = __hfma2(*(__half2*)&q1, *(__half2*)&k1, acc);
    }
    float2 f = __half22float2(acc);
    return f.x + f.y;
}

// 4 lanes per edge, 2 edges per group slot -> 16 edges per warp (MLP=4 champion).
// PDL: c/u index loads are independent of convert's output -> issue them BEFORE
// griddepcontrol.wait so they overlap the convert tail. Gather after the wait.
__global__ void edge_kernel(const int* __restrict__ c,
                            const int* __restrict__ u,
                            int num_edges) {
    const unsigned FULL = 0xffffffffu;
    int lane = threadIdx.x & 31;
    int grp  = lane >> 2;        // slot within warp (0..7)
    int li   = lane & 3;         // lane within 4-lane group
    int warp_id = (blockIdx.x * (blockDim.x >> 5)) + (threadIdx.x >> 5);
    int base = warp_id * 16;
    int e0 = base + grp;
    int e1 = base + 8 + grp;

    bool v0 = (e0 < num_edges);
    bool v1 = (e1 < num_edges);

    int c0 = 0, u0 = 0, c1 = 0, u1 = 0;
    if (v0) { c0 = c[e0]; u0 = u[e0]; }
    if (v1) { c1 = c[e1]; u1 = u[e1]; }

    // Wait for convert grid to complete before touching gQ8/gK8/g_node_sum.
    pdl_wait();

    float d0 = 0.0f, d1 = 0.0f;
    if (v0) {
        uint4 q = gQ8[c0 * 4 + li];
        uint4 k = gK8[u0 * 4 + li];
        d0 = dot_fp8_u4(q, k);
    }
    if (v1) {
        uint4 q = gQ8[c1 * 4 + li];
        uint4 k = gK8[u1 * 4 + li];
        d1 = dot_fp8_u4(q, k);
    }

    d0 += __shfl_xor_sync(FULL, d0, 1);
    d0 += __shfl_xor_sync(FULL, d0, 2);
    d1 += __shfl_xor_sync(FULL, d1, 1);
    d1 += __shfl_xor_sync(FULL, d1, 2);

    if (li == 0) {
        if (v0) atomicAdd(&g_node_sum[c0], __expf(d0 * 0.125f));
        if (v1) atomicAdd(&g_node_sum[c1], __expf(d1 * 0.125f));
    }

    pdl_launch_dependents();
}

// Per node: lse = log(sum) (0 for empty). batch is sorted -> warp-segmented
// reduction, only segment heads hit the per-graph atomic.
// PDL: batch load is independent of edge output -> load before the wait.
__global__ void node_kernel(const int* __restrict__ batch,
                            float* __restrict__ out,
                            int num_nodes) {
    const unsigned FULL = 0xffffffffu;
    int n = blockIdx.x * blockDim.x + threadIdx.x;
    int lane = threadIdx.x & 31;

    bool valid = (n < num_nodes);
    int b = -1;
    if (valid) b = batch[n];

    // Wait for edge grid (g_node_sum complete; transitively, out zeroed).
    pdl_wait();

    float v = 0.0f;
    if (valid) {
        float s = g_node_sum[n];
        v = (s > 0.0f) ? __logf(s) : 0.0f;
    }
    #pragma unroll
    for (int off = 1; off < 32; off <<= 1) {
        float ov = __shfl_down_sync(FULL, v, off);
        int   ob = __shfl_down_sync(FULL, b, off);
        if (lane + off < 32 && ob == b) v += ov;
    }
    int bprev = __shfl_up_sync(FULL, b, 1);
    bool head = (lane == 0) || (bprev != b);
    if (valid && head) {
        atomicAdd(&out[b], v);
    }
}

extern "C" void kernel_launch(void* const* d_in, const int* in_sizes, int n_in,
                              void* d_out, int out_size) {
    const float4* Q   = (const float4*)d_in[0];
    const float4* K   = (const float4*)d_in[1];
    const int* c      = (const int*)d_in[2];
    const int* u      = (const int*)d_in[3];
    const int* batch  = (const int*)d_in[4];

    int num_nodes  = in_sizes[0] / 64;
    int num_edges  = in_sizes[2];
    int num_graphs = out_size;
    float* out = (float*)d_out;

    // 1) convert + zero (normal launch, transposed coalesced mapping)
    {
        int total16 = num_nodes * 16;
        int blocks = 148 * 8;
        convert_zero_kernel<<<blocks, 256>>>(Q, K, out, total16,
                                             num_nodes, num_graphs);
    }
    // 2) edge kernel, PDL-dependent on convert
    {
        int threads = 256;
        int edges_per_block = (threads / 32) * 16;   // 128
        int blocks = (num_edges + edges_per_block - 1) / edges_per_block;

        cudaLaunchConfig_t cfg = {};
        cfg.gridDim = dim3((unsigned)blocks);
        cfg.blockDim = dim3((unsigned)threads);
        cudaLaunchAttribute attr[1];
        attr[0].id = cudaLaunchAttributeProgrammaticStreamSerialization;
        attr[0].val.programmaticStreamSerializationAllowed = 1;
        cfg.attrs = attr;
        cfg.numAttrs = 1;
        cudaLaunchKernelEx(&cfg, edge_kernel, c, u, num_edges);
    }
    // 3) node kernel, PDL-dependent on edge
    {
        int blocks = (num_nodes + 511) / 512;

        cudaLaunchConfig_t cfg = {};
        cfg.gridDim = dim3((unsigned)blocks);
        cfg.blockDim = dim3(512);
        cudaLaunchAttribute attr[1];
        attr[0].id = cudaLaunchAttributeProgrammaticStreamSerialization;
        attr[0].val.programmaticStreamSerializationAllowed = 1;
        cfg.attrs = attr;
        cfg.numAttrs = 1;
        cudaLaunchKernelEx(&cfg, node_kernel, batch, out, num_nodes);
    }
}

// round 12
// speedup vs baseline: 1.1244x; 1.0006x over previous
#include <cuda_runtime.h>
#include <cuda_bf16.h>
#include <cuda_fp8.h>
#include <math.h>

// ----- scratch (no allocations allowed) -----
#define NODE_CAP 131072
__device__ float g_node_sum[NODE_CAP];
// fp8(e4m3) copies of Q,K: one row = 64 fp8 = 64 B = 4 uint4
__device__ uint4 gQ8[NODE_CAP * 4];
__device__ uint4 gK8[NODE_CAP * 4];

// --- PDL primitives (sm_90+) ---
__device__ __forceinline__ void pdl_wait() {
    asm volatile("griddepcontrol.wait;" ::: "memory");
}
__device__ __forceinline__ void pdl_launch_dependents() {
    asm volatile("griddepcontrol.launch_dependents;" ::: "memory");
}

__device__ __forceinline__ unsigned pack4_fp8(float4 a) {
    unsigned short lo = __nv_cvt_float2_to_fp8x2(make_float2(a.x, a.y), __NV_SATFINITE, __NV_E4M3);
    unsigned short hi = __nv_cvt_float2_to_fp8x2(make_float2(a.z, a.w), __NV_SATFINITE, __NV_E4M3);
    return (unsigned)lo | ((unsigned)hi << 16);
}

// fp32 -> fp8 conversion, transposed coalesced mapping (thread i -> one float4),
// manually unrolled 2x (indices i and i+stride) so 4 LDG.128 are in flight.
// Fused zeroing of g_node_sum and out.
__global__ void convert_zero_kernel(const float4* __restrict__ Q,
                                    const float4* __restrict__ K,
                                    float* __restrict__ out,
                                    int total16 /* num_nodes*16 */,
                                    int num_nodes, int num_graphs) {
    unsigned* dQ = (unsigned*)gQ8;
    unsigned* dK = (unsigned*)gK8;
    int stride = gridDim.x * blockDim.x;
    int i = blockIdx.x * blockDim.x + threadIdx.x;
    if (i < num_nodes) g_node_sum[i] = 0.0f;
    if (i < num_graphs) out[i] = 0.0f;

    for (; i + stride < total16; i += 2 * stride) {
        int j = i + stride;
        float4 q0 = Q[i];
        float4 k0 = K[i];
        float4 q1 = Q[j];
        float4 k1 = K[j];
        dQ[i] = pack4_fp8(q0);
        dK[i] = pack4_fp8(k0);
        dQ[j] = pack4_fp8(q1);
        dK[j] = pack4_fp8(k1);
    }
    if (i < total16) {
        float4 q0 = Q[i];
        float4 k0 = K[i];
        dQ[i] = pack4_fp8(q0);
        dK[i] = pack4_fp8(k0);
    }
    pdl_launch_dependents();
}

__device__ __forceinline__ float dot_fp8_u4(uint4 q, uint4 k) {
    __half2 acc = __floats2half2_rn(0.0f, 0.0f);
    #pragma unroll
    for (int j = 0; j < 4; j++) {
        unsigned qw = (&q.x)[j];
        unsigned kw = (&k.x)[j];
        __half2_raw q0 = __nv_cvt_fp8x2_to_halfraw2((__nv_fp8x2_storage_t)(qw & 0xffffu), __NV_E4M3);
        __half2_raw q1 = __nv_cvt_fp8x2_to_halfraw2((__nv_fp8x2_storage_t)(qw >> 16),     __NV_E4M3);
        __half2_raw k0 = __nv_cvt_fp8x2_to_halfraw2((__nv_fp8x2_storage_t)(kw & 0xffffu), __NV_E4M3);
        __half2_raw k1 = __nv_cvt_fp8x2_to_halfraw2((__nv_fp8x2_storage_t)(kw >> 16),     __NV_E4M3);
        acc = __hfma2(*(__half2*)&q0, *(__half2*)&k0, acc);
        acc = __hfma2(*(__half2*)&q1, *(__half2*)&k1, acc);
    }
    float2 f = __half22float2(acc);
    return f.x + f.y;
}

// 4 lanes per edge, 2 edges per group slot -> 16 edges per warp (MLP=4 champion).
// PDL: c/u index loads issued BEFORE griddepcontrol.wait (independent of convert).
// launch_dependents hoisted above the atomics: node grid may launch early; its
// own griddepcontrol.wait still blocks until this grid fully completes.
__global__ void edge_kernel(const int* __restrict__ c,
                            const int* __restrict__ u,
                            int num_edges) {
    const unsigned FULL = 0xffffffffu;
    int lane = threadIdx.x & 31;
    int grp  = lane >> 2;        // slot within warp (0..7)
    int li   = lane & 3;         // lane within 4-lane group
    int warp_id = (blockIdx.x * (blockDim.x >> 5)) + (threadIdx.x >> 5);
    int base = warp_id * 16;
    int e0 = base + grp;
    int e1 = base + 8 + grp;

    bool v0 = (e0 < num_edges);
    bool v1 = (e1 < num_edges);

    int c0 = 0, u0 = 0, c1 = 0, u1 = 0;
    if (v0) { c0 = c[e0]; u0 = u[e0]; }
    if (v1) { c1 = c[e1]; u1 = u[e1]; }

    // Wait for convert grid to complete before touching gQ8/gK8/g_node_sum.
    pdl_wait();

    float d0 = 0.0f, d1 = 0.0f;
    if (v0) {
        uint4 q = gQ8[c0 * 4 + li];
        uint4 k = gK8[u0 * 4 + li];
        d0 = dot_fp8_u4(q, k);
    }
    if (v1) {
        uint4 q = gQ8[c1 * 4 + li];
        uint4 k = gK8[u1 * 4 + li];
        d1 = dot_fp8_u4(q, k);
    }

    d0 += __shfl_xor_sync(FULL, d0, 1);
    d0 += __shfl_xor_sync(FULL, d0, 2);
    d1 += __shfl_xor_sync(FULL, d1, 1);
    d1 += __shfl_xor_sync(FULL, d1, 2);

    pdl_launch_dependents();

    if (li == 0) {
        if (v0) atomicAdd(&g_node_sum[c0], __expf(d0 * 0.125f));
        if (v1) atomicAdd(&g_node_sum[c1], __expf(d1 * 0.125f));
    }
}

// Per node: lse = log(sum) (0 for empty). batch is sorted -> warp-segmented
// reduction, only segment heads hit the per-graph atomic.
// PDL: batch load is independent of edge output -> load before the wait.
__global__ void node_kernel(const int* __restrict__ batch,
                            float* __restrict__ out,
                            int num_nodes) {
    const unsigned FULL = 0xffffffffu;
    int n = blockIdx.x * blockDim.x + threadIdx.x;
    int lane = threadIdx.x & 31;

    bool valid = (n < num_nodes);
    int b = -1;
    if (valid) b = batch[n];

    // Wait for edge grid (g_node_sum complete; transitively, out zeroed).
    pdl_wait();

    float v = 0.0f;
    if (valid) {
        float s = g_node_sum[n];
        v = (s > 0.0f) ? __logf(s) : 0.0f;
    }
    #pragma unroll
    for (int off = 1; off < 32; off <<= 1) {
        float ov = __shfl_down_sync(FULL, v, off);
        int   ob = __shfl_down_sync(FULL, b, off);
        if (lane + off < 32 && ob == b) v += ov;
    }
    int bprev = __shfl_up_sync(FULL, b, 1);
    bool head = (lane == 0) || (bprev != b);
    if (valid && head) {
        atomicAdd(&out[b], v);
    }
}

extern "C" void kernel_launch(void* const* d_in, const int* in_sizes, int n_in,
                              void* d_out, int out_size) {
    const float4* Q   = (const float4*)d_in[0];
    const float4* K   = (const float4*)d_in[1];
    const int* c      = (const int*)d_in[2];
    const int* u      = (const int*)d_in[3];
    const int* batch  = (const int*)d_in[4];

    int num_nodes  = in_sizes[0] / 64;
    int num_edges  = in_sizes[2];
    int num_graphs = out_size;
    float* out = (float*)d_out;

    // 1) convert + zero (normal launch, transposed coalesced mapping, 2x unroll)
    {
        int total16 = num_nodes * 16;
        int blocks = 148 * 8;
        convert_zero_kernel<<<blocks, 256>>>(Q, K, out, total16,
                                             num_nodes, num_graphs);
    }
    // 2) edge kernel, PDL-dependent on convert
    {
        int threads = 256;
        int edges_per_block = (threads / 32) * 16;   // 128
        int blocks = (num_edges + edges_per_block - 1) / edges_per_block;

        cudaLaunchConfig_t cfg = {};
        cfg.gridDim = dim3((unsigned)blocks);
        cfg.blockDim = dim3((unsigned)threads);
        cudaLaunchAttribute attr[1];
        attr[0].id = cudaLaunchAttributeProgrammaticStreamSerialization;
        attr[0].val.programmaticStreamSerializationAllowed = 1;
        cfg.attrs = attr;
        cfg.numAttrs = 1;
        cudaLaunchKernelEx(&cfg, edge_kernel, c, u, num_edges);
    }
    // 3) node kernel, PDL-dependent on edge
    {
        int blocks = (num_nodes + 511) / 512;

        cudaLaunchConfig_t cfg = {};
        cfg.gridDim = dim3((unsigned)blocks);
        cfg.blockDim = dim3(512);
        cudaLaunchAttribute attr[1];
        attr[0].id = cudaLaunchAttributeProgrammaticStreamSerialization;
        attr[0].val.programmaticStreamSerializationAllowed = 1;
        cfg.attrs = attr;
        cfg.numAttrs = 1;
        cudaLaunchKernelEx(&cfg, node_kernel, batch, out, num_nodes);
    }
}